// round 8
// baseline (speedup 1.0000x reference)
#include <cuda_runtime.h>

#define NN  1024
#define RAW 128
#define DD  128
#define HH  256

#define SELU_ALPHA 1.6732632423543772f
#define SELU_SCALE 1.0507009873554805f

typedef unsigned long long ull;

#define UNPACK2(lo, hi, s) asm("mov.b64 {%0, %1}, %2;" : "=f"(lo), "=f"(hi) : "l"(s))
#define MULSAT(d, a, b)  asm("mul.rn.sat.f32 %0, %1, %2;" : "=f"(d) : "f"(a), "f"(b))
#define CP16(dst, src) \
    asm volatile("cp.async.cg.shared.global [%0], [%1], 16;" \
                 :: "r"((unsigned)(dst)), "l"(src))
#define CP_COMMIT() asm volatile("cp.async.commit_group;" ::: "memory")
#define CP_WAIT0()  asm volatile("cp.async.wait_group 0;" ::: "memory")

// Scratch (static __device__ arrays; no allocation)
__device__ float  g_AT  [HH * NN];   // A^T (incl. b1)            [k][j]
__device__ float  g_EAT [HH * NN];   // exp(A^T)                  [k][j]
__device__ float2 g_BTD [HH * NN];   // {B,B} dup-packed          [k][i]
__device__ float  g_EBT [HH * NN];   // exp(B^T)                  [k][i]
__device__ float  g_P   [NN];        // P[j] = sum_k (sw_k/2) A[k][j]
__device__ float  g_Q   [NN];        // Q[i] = sum_k (sw_k/2) B[k][i]
__device__ float4 g_hwaw[HH];        // {sw/2, sw/2, asw, asw}
__device__ float  g_c0;              // b2 - sum asw

// ---------------------------------------------------------------------------
// Fused aux (unchanged from R6): prep + z + A/B GEMMs + exp + transposed
// stores + P/Q.  256 blocks x 256 threads, 4 rows/blk.
// ---------------------------------------------------------------------------
__global__ __launch_bounds__(256) void aux_kernel(
        const float* __restrict__ x,     const float* __restrict__ W_enc,
        const float* __restrict__ b_enc, const float* __restrict__ W1,
        const float* __restrict__ b1,    const float* __restrict__ W2,
        const float* __restrict__ b2) {
    __shared__ float sx [4][RAW];
    __shared__ float sz [4][DD];
    __shared__ float swa[16 * 256];
    __shared__ float swb[16 * 256];
    __shared__ float stV[HH * 5];
    __shared__ float stE[HH * 5];
    __shared__ float redR[8][4];

    const int t  = threadIdx.x;          // k in [0,256)
    const int j0 = blockIdx.x * 4;

    if (blockIdx.x == 0) {
        float w   = W2[t];
        float sw  = SELU_SCALE * w;
        float asw = SELU_ALPHA * sw;
        float hw  = 0.5f * sw;
        g_hwaw[t] = make_float4(hw, hw, asw, asw);
        stV[t] = asw;
        __syncthreads();
        #pragma unroll
        for (int s = 128; s > 0; s >>= 1) {
            if (t < s) stV[t] += stV[t + s];
            __syncthreads();
        }
        if (t == 0) g_c0 = b2[0] - stV[0];
        __syncthreads();
    }

    #pragma unroll
    for (int s = 0; s < 2; s++) {
        int idx = t + s * 256;
        sx[idx >> 7][idx & 127] = x[(j0 + (idx >> 7)) * RAW + (idx & 127)];
    }
    __syncthreads();

    {
        const int k  = t & 127;
        const int rh = t >> 7;
        float za0 = 0.f, za1 = 0.f;
        for (int c0 = 0; c0 < RAW; c0 += 16) {
            const float4* src = reinterpret_cast<const float4*>(W_enc + c0 * DD);
            float4* dst = reinterpret_cast<float4*>(swa);
            dst[t]       = src[t];
            dst[t + 256] = src[t + 256];
            __syncthreads();
            #pragma unroll
            for (int cc = 0; cc < 16; cc++) {
                float w = swa[cc * DD + k];
                za0 = fmaf(sx[2 * rh][c0 + cc],     w, za0);
                za1 = fmaf(sx[2 * rh + 1][c0 + cc], w, za1);
            }
            __syncthreads();
        }
        float bb = b_enc[k];
        sz[2 * rh][k]     = za0 + bb;
        sz[2 * rh + 1][k] = za1 + bb;
    }
    __syncthreads();

    float accA[4] = {0.f, 0.f, 0.f, 0.f};
    float accB[4] = {0.f, 0.f, 0.f, 0.f};
    for (int c0 = 0; c0 < DD; c0 += 16) {
        const float4* srcA = reinterpret_cast<const float4*>(W1 + c0 * HH);
        const float4* srcB = reinterpret_cast<const float4*>(W1 + (c0 + DD) * HH);
        float4* dstA = reinterpret_cast<float4*>(swa);
        float4* dstB = reinterpret_cast<float4*>(swb);
        #pragma unroll
        for (int s = 0; s < 4; s++) {
            dstA[t + s * 256] = srcA[t + s * 256];
            dstB[t + s * 256] = srcB[t + s * 256];
        }
        __syncthreads();
        #pragma unroll
        for (int cc = 0; cc < 16; cc++) {
            float wa = swa[cc * HH + t];
            float wb = swb[cc * HH + t];
            #pragma unroll
            for (int r = 0; r < 4; r++) {
                float zz = sz[r][c0 + cc];
                accA[r] = fmaf(zz, wa, accA[r]);
                accB[r] = fmaf(zz, wb, accB[r]);
            }
        }
        __syncthreads();
    }

    const float b1k = b1[t];
    const float hw  = 0.5f * SELU_SCALE * W2[t];
    const int wid = t >> 5, lid = t & 31;

    {
        float pv[4];
        #pragma unroll
        for (int r = 0; r < 4; r++) {
            float a = accA[r] + b1k;
            stV[t * 5 + r] = a;
            stE[t * 5 + r] = __expf(fminf(fmaxf(a, -60.f), 60.f));
            pv[r] = hw * a;
        }
        #pragma unroll
        for (int r = 0; r < 4; r++) {
            float v = pv[r];
            #pragma unroll
            for (int s = 16; s > 0; s >>= 1)
                v += __shfl_down_sync(0xffffffffu, v, s);
            if (lid == 0) redR[wid][r] = v;
        }
        __syncthreads();
        #pragma unroll
        for (int p = 0; p < 4; p++) {
            int idx = p * 256 + t;
            int k = idx >> 2, j = idx & 3;
            g_AT [k * NN + j0 + j] = stV[k * 5 + j];
            g_EAT[k * NN + j0 + j] = stE[k * 5 + j];
        }
        if (t < 4) {
            float s = 0.f;
            #pragma unroll
            for (int w2i = 0; w2i < 8; w2i++) s += redR[w2i][t];
            g_P[j0 + t] = s;
        }
        __syncthreads();
    }

    {
        float pv[4];
        #pragma unroll
        for (int r = 0; r < 4; r++) {
            float b = accB[r];
            stV[t * 5 + r] = b;
            stE[t * 5 + r] = __expf(fminf(fmaxf(b, -60.f), 60.f));
            pv[r] = hw * b;
        }
        #pragma unroll
        for (int r = 0; r < 4; r++) {
            float v = pv[r];
            #pragma unroll
            for (int s = 16; s > 0; s >>= 1)
                v += __shfl_down_sync(0xffffffffu, v, s);
            if (lid == 0) redR[wid][r] = v;
        }
        __syncthreads();
        #pragma unroll
        for (int p = 0; p < 4; p++) {
            int idx = p * 256 + t;
            int k = idx >> 2, j = idx & 3;
            float b = stV[k * 5 + j];
            g_BTD[k * NN + j0 + j] = make_float2(b, b);
            g_EBT[k * NN + j0 + j] = stE[k * 5 + j];
        }
        if (t < 4) {
            float s = 0.f;
            #pragma unroll
            for (int w2i = 0; w2i < 8; w2i++) s += redR[w2i][t];
            g_Q[j0 + t] = s;
        }
    }
}

// ---------------------------------------------------------------------------
// Main: o[i,j] = hsig( P[j] + Q[i] + c0 + sum_k [ hw_k*|v| + asw_k*sat(e) ] )
// 32x32 tiles, 128 threads (4j x 2i per thread), grid 1024, 6 CTAs/SM.
// Double-buffered cp.async, fused-asm packed relu half, scalar e half.
// ---------------------------------------------------------------------------
__global__ __launch_bounds__(128, 6) void main_kernel(float* __restrict__ out) {
    __shared__ float4 s_a [2][16][8];    // [buf][k][j4]
    __shared__ float4 s_ea[2][16][8];
    __shared__ ull    s_bd[2][16][32];   // [buf][k][i] dup pairs {b,b}
    __shared__ float4 s_eb[2][16][8];    // [buf][k][i4]
    __shared__ float4 s_wa[2][16];       // {hw,hw,asw,asw}

    const int tid = threadIdx.x;
    const int tx  = tid & 7;     // j quad (32 j / 4)
    const int ty  = tid >> 3;    // i pair (0..15), i = 2*ty + {0,1}
    const int j0  = blockIdx.x * 32;
    const int i0  = blockIdx.y * 32;

    const float4* AT4  = reinterpret_cast<const float4*>(g_AT);
    const float4* EAT4 = reinterpret_cast<const float4*>(g_EAT);
    const float4* EBT4 = reinterpret_cast<const float4*>(g_EBT);

    const ull MASK = 0x7FFFFFFF7FFFFFFFull;

    // loader coords
    const int lk = tid >> 3, lq = tid & 7;           // a/ea/eb: k row, quad
    const int b0k = tid >> 4,        b0c = tid & 15; // bd chunk 0 (k 0..7)
    const int b1k = (tid + 128) >> 4, b1c = tid & 15;// bd chunk 1 (k 8..15)

    ull   accP[2][2];
    float accE[2][4];
    #pragma unroll
    for (int i = 0; i < 2; i++) {
        accP[i][0] = 0ull; accP[i][1] = 0ull;
        #pragma unroll
        for (int j = 0; j < 4; j++) accE[i][j] = 0.f;
    }

    // ---- issue chunk 0 loads ----
    {
        int ga = lk * (NN / 4) + (j0 >> 2) + lq;
        int gb = lk * (NN / 4) + (i0 >> 2) + lq;
        CP16(__cvta_generic_to_shared(&s_a [0][lk][lq]), AT4  + ga);
        CP16(__cvta_generic_to_shared(&s_ea[0][lk][lq]), EAT4 + ga);
        CP16(__cvta_generic_to_shared(&s_eb[0][lk][lq]), EBT4 + gb);
        CP16(__cvta_generic_to_shared(&s_bd[0][b0k][b0c * 2]),
             reinterpret_cast<const ulonglong2*>(&g_BTD[b0k * NN + i0]) + b0c);
        CP16(__cvta_generic_to_shared(&s_bd[0][b1k][b1c * 2]),
             reinterpret_cast<const ulonglong2*>(&g_BTD[b1k * NN + i0]) + b1c);
        if (tid < 16)
            CP16(__cvta_generic_to_shared(&s_wa[0][tid]), &g_hwaw[tid]);
        CP_COMMIT();
    }

    int buf = 0;
    for (int c = 0; c < 16; c++) {
        CP_WAIT0();
        __syncthreads();

        if (c < 15) {
            int k0 = (c + 1) * 16;
            int nb = buf ^ 1;
            int ga = (k0 + lk) * (NN / 4) + (j0 >> 2) + lq;
            int gb = (k0 + lk) * (NN / 4) + (i0 >> 2) + lq;
            CP16(__cvta_generic_to_shared(&s_a [nb][lk][lq]), AT4  + ga);
            CP16(__cvta_generic_to_shared(&s_ea[nb][lk][lq]), EAT4 + ga);
            CP16(__cvta_generic_to_shared(&s_eb[nb][lk][lq]), EBT4 + gb);
            CP16(__cvta_generic_to_shared(&s_bd[nb][b0k][b0c * 2]),
                 reinterpret_cast<const ulonglong2*>(&g_BTD[(k0 + b0k) * NN + i0]) + b0c);
            CP16(__cvta_generic_to_shared(&s_bd[nb][b1k][b1c * 2]),
                 reinterpret_cast<const ulonglong2*>(&g_BTD[(k0 + b1k) * NN + i0]) + b1c);
            if (tid < 16)
                CP16(__cvta_generic_to_shared(&s_wa[nb][tid]), &g_hwaw[k0 + tid]);
            CP_COMMIT();
        }

        #pragma unroll
        for (int kk = 0; kk < 16; kk++) {
            ulonglong2 a2 = *reinterpret_cast<const ulonglong2*>(&s_a[buf][kk][tx]);
            float4     ea = s_ea[buf][kk][tx];
            ulonglong2 bd = *reinterpret_cast<const ulonglong2*>(&s_bd[buf][kk][ty * 2]);
            float2     eb = *reinterpret_cast<const float2*>(
                                reinterpret_cast<const float*>(&s_eb[buf][kk][0]) + ty * 2);
            float4     wa = s_wa[buf][kk];
            ull w2; asm("mov.b64 %0, {%1, %2};" : "=l"(w2) : "f"(wa.x), "f"(wa.y));
            float asw = wa.z;

            ull   ap[2]  = {a2.x, a2.y};
            ull   bp[2]  = {bd.x, bd.y};
            float eav[4] = {ea.x, ea.y, ea.z, ea.w};
            float ebv[2] = {eb.x, eb.y};

            #pragma unroll
            for (int i = 0; i < 2; i++) {
                #pragma unroll
                for (int jp = 0; jp < 2; jp++) {
                    // packed relu half: acc += |a+b| * hw2
                    asm("{\n\t"
                        ".reg .b64 v;\n\t"
                        "add.rn.f32x2 v, %1, %2;\n\t"
                        "and.b64 v, v, %3;\n\t"
                        "fma.rn.f32x2 %0, v, %4, %0;\n\t"
                        "}"
                        : "+l"(accP[i][jp])
                        : "l"(ap[jp]), "l"(bp[i]), "l"(MASK), "l"(w2));
                    // scalar e half: accE += sat(ea*eb) * asw
                    float e0, e1;
                    MULSAT(e0, eav[2 * jp],     ebv[i]);
                    MULSAT(e1, eav[2 * jp + 1], ebv[i]);
                    accE[i][2 * jp]     = fmaf(e0, asw, accE[i][2 * jp]);
                    accE[i][2 * jp + 1] = fmaf(e1, asw, accE[i][2 * jp + 1]);
                }
            }
        }
        buf ^= 1;
    }

    // epilogue: + P[j] + Q[i] + c0, hard_sigmoid
    const float c0 = g_c0;
    float4 Pv = *reinterpret_cast<const float4*>(&g_P[j0 + tx * 4]);
    #pragma unroll
    for (int i = 0; i < 2; i++) {
        int   irow = i0 + ty * 2 + i;
        float base = g_Q[irow] + c0 + 3.0f;
        float p0, p1, p2, p3;
        UNPACK2(p0, p1, accP[i][0]);
        UNPACK2(p2, p3, accP[i][1]);
        float4 o;
        o.x = fminf(fmaxf(p0 + accE[i][0] + Pv.x + base, 0.f), 6.f) * (1.f / 6.f);
        o.y = fminf(fmaxf(p1 + accE[i][1] + Pv.y + base, 0.f), 6.f) * (1.f / 6.f);
        o.z = fminf(fmaxf(p2 + accE[i][2] + Pv.z + base, 0.f), 6.f) * (1.f / 6.f);
        o.w = fminf(fmaxf(p3 + accE[i][3] + Pv.w + base, 0.f), 6.f) * (1.f / 6.f);
        *reinterpret_cast<float4*>(&out[irow * NN + j0 + tx * 4]) = o;
    }
}

// ---------------------------------------------------------------------------
extern "C" void kernel_launch(void* const* d_in, const int* in_sizes, int n_in,
                              void* d_out, int out_size) {
    const float* x     = (const float*)d_in[0];
    const float* W_enc = (const float*)d_in[1];
    const float* b_enc = (const float*)d_in[2];
    const float* W1    = (const float*)d_in[3];
    const float* b1    = (const float*)d_in[4];
    const float* W2    = (const float*)d_in[5];
    const float* b2    = (const float*)d_in[6];
    float* out = (float*)d_out;

    aux_kernel<<<NN / 4, 256>>>(x, W_enc, b_enc, W1, b1, W2, b2);

    dim3 grid(NN / 32, NN / 32);
    main_kernel<<<grid, 128>>>(out);
}

// round 9
// speedup vs baseline: 1.1237x; 1.1237x over previous
#include <cuda_runtime.h>

#define NN  1024
#define RAW 128
#define DD  128
#define HH  256

#define SELU_ALPHA 1.6732632423543772f
#define SELU_SCALE 1.0507009873554805f

typedef unsigned long long ull;

#define UNPACK2(lo, hi, s) asm("mov.b64 {%0, %1}, %2;" : "=f"(lo), "=f"(hi) : "l"(s))
#define PACK2(d, lo, hi)   asm("mov.b64 %0, {%1, %2};" : "=l"(d) : "f"(lo), "f"(hi))
#define MULSAT(d, a, b)    asm("mul.rn.sat.f32 %0, %1, %2;" : "=f"(d) : "f"(a), "f"(b))

// Scratch (static __device__ arrays; no allocation)
__device__ float  g_AT  [HH * NN];   // A^T (incl. b1)            [k][j]
__device__ float  g_EAT [HH * NN];   // exp(A^T)                  [k][j]
__device__ float  g_BT  [HH * NN];   // B^T                       [k][i]
__device__ float  g_EBT [HH * NN];   // exp(B^T)                  [k][i]
__device__ float  g_P   [NN];        // P[j] = sum_k (sw_k/2) A[k][j]
__device__ float  g_Q   [NN];        // Q[i] = sum_k (sw_k/2) B[k][i]
__device__ float4 g_hwaw[HH];        // {sw/2, sw/2, asw, asw}
__device__ float  g_c0;              // b2 - sum asw

// ---------------------------------------------------------------------------
// Fused aux: prep (block 0) + z + A/B GEMMs (smem-staged weights) + exp +
// transposed stores + P/Q rank-1 terms.  256 blocks x 256 threads, 4 rows/blk.
// ---------------------------------------------------------------------------
__global__ __launch_bounds__(256) void aux_kernel(
        const float* __restrict__ x,     const float* __restrict__ W_enc,
        const float* __restrict__ b_enc, const float* __restrict__ W1,
        const float* __restrict__ b1,    const float* __restrict__ W2,
        const float* __restrict__ b2) {
    __shared__ float sx [4][RAW];
    __shared__ float sz [4][DD];
    __shared__ float swa[16 * 256];
    __shared__ float swb[16 * 256];
    __shared__ float stV[HH * 5];
    __shared__ float stE[HH * 5];
    __shared__ float redR[8][4];

    const int t  = threadIdx.x;          // k in [0,256)
    const int j0 = blockIdx.x * 4;

    if (blockIdx.x == 0) {
        float w   = W2[t];
        float sw  = SELU_SCALE * w;
        float asw = SELU_ALPHA * sw;
        float hw  = 0.5f * sw;
        g_hwaw[t] = make_float4(hw, hw, asw, asw);
        stV[t] = asw;
        __syncthreads();
        #pragma unroll
        for (int s = 128; s > 0; s >>= 1) {
            if (t < s) stV[t] += stV[t + s];
            __syncthreads();
        }
        if (t == 0) g_c0 = b2[0] - stV[0];
        __syncthreads();
    }

    #pragma unroll
    for (int s = 0; s < 2; s++) {
        int idx = t + s * 256;
        sx[idx >> 7][idx & 127] = x[(j0 + (idx >> 7)) * RAW + (idx & 127)];
    }
    __syncthreads();

    {
        const int k  = t & 127;
        const int rh = t >> 7;
        float za0 = 0.f, za1 = 0.f;
        for (int c0 = 0; c0 < RAW; c0 += 16) {
            const float4* src = reinterpret_cast<const float4*>(W_enc + c0 * DD);
            float4* dst = reinterpret_cast<float4*>(swa);
            dst[t]       = src[t];
            dst[t + 256] = src[t + 256];
            __syncthreads();
            #pragma unroll
            for (int cc = 0; cc < 16; cc++) {
                float w = swa[cc * DD + k];
                za0 = fmaf(sx[2 * rh][c0 + cc],     w, za0);
                za1 = fmaf(sx[2 * rh + 1][c0 + cc], w, za1);
            }
            __syncthreads();
        }
        float bb = b_enc[k];
        sz[2 * rh][k]     = za0 + bb;
        sz[2 * rh + 1][k] = za1 + bb;
    }
    __syncthreads();

    float accA[4] = {0.f, 0.f, 0.f, 0.f};
    float accB[4] = {0.f, 0.f, 0.f, 0.f};
    for (int c0 = 0; c0 < DD; c0 += 16) {
        const float4* srcA = reinterpret_cast<const float4*>(W1 + c0 * HH);
        const float4* srcB = reinterpret_cast<const float4*>(W1 + (c0 + DD) * HH);
        float4* dstA = reinterpret_cast<float4*>(swa);
        float4* dstB = reinterpret_cast<float4*>(swb);
        #pragma unroll
        for (int s = 0; s < 4; s++) {
            dstA[t + s * 256] = srcA[t + s * 256];
            dstB[t + s * 256] = srcB[t + s * 256];
        }
        __syncthreads();
        #pragma unroll
        for (int cc = 0; cc < 16; cc++) {
            float wa = swa[cc * HH + t];
            float wb = swb[cc * HH + t];
            #pragma unroll
            for (int r = 0; r < 4; r++) {
                float zz = sz[r][c0 + cc];
                accA[r] = fmaf(zz, wa, accA[r]);
                accB[r] = fmaf(zz, wb, accB[r]);
            }
        }
        __syncthreads();
    }

    const float b1k = b1[t];
    const float hw  = 0.5f * SELU_SCALE * W2[t];
    const int wid = t >> 5, lid = t & 31;

    // ---- round A: AT/EAT stores + P ----
    {
        float pv[4];
        #pragma unroll
        for (int r = 0; r < 4; r++) {
            float a = accA[r] + b1k;
            stV[t * 5 + r] = a;
            stE[t * 5 + r] = __expf(fminf(fmaxf(a, -60.f), 60.f));
            pv[r] = hw * a;
        }
        #pragma unroll
        for (int r = 0; r < 4; r++) {
            float v = pv[r];
            #pragma unroll
            for (int s = 16; s > 0; s >>= 1)
                v += __shfl_down_sync(0xffffffffu, v, s);
            if (lid == 0) redR[wid][r] = v;
        }
        __syncthreads();
        #pragma unroll
        for (int p = 0; p < 4; p++) {
            int idx = p * 256 + t;
            int k = idx >> 2, j = idx & 3;
            g_AT [k * NN + j0 + j] = stV[k * 5 + j];
            g_EAT[k * NN + j0 + j] = stE[k * 5 + j];
        }
        if (t < 4) {
            float s = 0.f;
            #pragma unroll
            for (int w2i = 0; w2i < 8; w2i++) s += redR[w2i][t];
            g_P[j0 + t] = s;
        }
        __syncthreads();
    }

    // ---- round B: BT/EBT stores + Q ----
    {
        float pv[4];
        #pragma unroll
        for (int r = 0; r < 4; r++) {
            float b = accB[r];
            stV[t * 5 + r] = b;
            stE[t * 5 + r] = __expf(fminf(fmaxf(b, -60.f), 60.f));
            pv[r] = hw * b;
        }
        #pragma unroll
        for (int r = 0; r < 4; r++) {
            float v = pv[r];
            #pragma unroll
            for (int s = 16; s > 0; s >>= 1)
                v += __shfl_down_sync(0xffffffffu, v, s);
            if (lid == 0) redR[wid][r] = v;
        }
        __syncthreads();
        #pragma unroll
        for (int p = 0; p < 4; p++) {
            int idx = p * 256 + t;
            int k = idx >> 2, j = idx & 3;
            g_BT [k * NN + j0 + j] = stV[k * 5 + j];
            g_EBT[k * NN + j0 + j] = stE[k * 5 + j];
        }
        if (t < 4) {
            float s = 0.f;
            #pragma unroll
            for (int w2i = 0; w2i < 8; w2i++) s += redR[w2i][t];
            g_Q[j0 + t] = s;
        }
    }
}

// ---------------------------------------------------------------------------
// Main: o[i,j] = hsig( P[j] + Q[i] + c0 + sum_k [ hw_k*|v| + asw_k*sat(e) ] )
//   v = A[k][j]+B[k][i], e = EA[k][j]*EB[k][i] = exp(v), sat(e) = min(e,1).
// R3 skeleton: 64x64 tiles, 256 threads (4x4/thread), register prefetch of
// the next 16-k chunk, two __syncthreads per chunk, plain LDG/STS.
// Core: packed relu half (ADD2/AND/FMA2) + scalar e half (MULSAT/FFMA).
// ---------------------------------------------------------------------------
__global__ __launch_bounds__(256, 2) void main_kernel(float* __restrict__ out) {
    __shared__ float4 s_a [16][16];   // [k][j4]
    __shared__ float4 s_ea[16][16];
    __shared__ float4 s_b [16][16];   // [k][i4]
    __shared__ float4 s_eb[16][16];
    __shared__ float4 s_wa[16];       // {hw,hw,asw,asw}

    const int tid = threadIdx.x;
    const int tx  = tid & 15;    // j quad
    const int ty  = tid >> 4;    // i quad
    const int j0  = blockIdx.x * 64;
    const int i0  = blockIdx.y * 64;

    const float4* AT4  = reinterpret_cast<const float4*>(g_AT);
    const float4* EAT4 = reinterpret_cast<const float4*>(g_EAT);
    const float4* BT4  = reinterpret_cast<const float4*>(g_BT);
    const float4* EBT4 = reinterpret_cast<const float4*>(g_EBT);

    const int ar = tid >> 4, ac = tid & 15;   // tile loader coords
    const ull MASK = 0x7FFFFFFF7FFFFFFFull;

    const int gja = ar * (NN / 4) + (j0 >> 2) + ac;
    const int gib = ar * (NN / 4) + (i0 >> 2) + ac;

    ull   accP[4][2];
    float accE[4][4];
    #pragma unroll
    for (int i = 0; i < 4; i++) {
        accP[i][0] = 0ull; accP[i][1] = 0ull;
        #pragma unroll
        for (int j = 0; j < 4; j++) accE[i][j] = 0.f;
    }

    // prefetch chunk 0 into registers
    float4 pa, pea, pb, peb, pwa;
    pa  = AT4 [gja];
    pea = EAT4[gja];
    pb  = BT4 [gib];
    peb = EBT4[gib];
    if (tid < 16) pwa = g_hwaw[tid];

    for (int c = 0; c < 16; c++) {
        __syncthreads();
        s_a [ar][ac] = pa;
        s_ea[ar][ac] = pea;
        s_b [ar][ac] = pb;
        s_eb[ar][ac] = peb;
        if (tid < 16) s_wa[tid] = pwa;
        __syncthreads();

        if (c < 15) {
            int oa = (c + 1) * 16 * (NN / 4);
            pa  = AT4 [gja + oa];
            pea = EAT4[gja + oa];
            pb  = BT4 [gib + oa];
            peb = EBT4[gib + oa];
            if (tid < 16) pwa = g_hwaw[(c + 1) * 16 + tid];
        }

        #pragma unroll
        for (int kk = 0; kk < 16; kk++) {
            ulonglong2 a2 = *reinterpret_cast<const ulonglong2*>(&s_a[kk][tx]);
            float4     ea = s_ea[kk][tx];
            float4     b4 = s_b [kk][ty];
            float4     eb = s_eb[kk][ty];
            float4     wa = s_wa[kk];

            ull w2;
            PACK2(w2, wa.x, wa.y);
            const float asw = wa.z;

            ull   ap[2]  = {a2.x, a2.y};
            float bv [4] = {b4.x, b4.y, b4.z, b4.w};
            float eav[4] = {ea.x, ea.y, ea.z, ea.w};
            float ebv[4] = {eb.x, eb.y, eb.z, eb.w};

            #pragma unroll
            for (int i = 0; i < 4; i++) {
                ull b2;
                PACK2(b2, bv[i], bv[i]);
                #pragma unroll
                for (int jp = 0; jp < 2; jp++) {
                    // packed relu half: accP += |a+b| * {hw,hw}
                    asm("{\n\t"
                        ".reg .b64 v;\n\t"
                        "add.rn.f32x2 v, %1, %2;\n\t"
                        "and.b64 v, v, %3;\n\t"
                        "fma.rn.f32x2 %0, v, %4, %0;\n\t"
                        "}"
                        : "+l"(accP[i][jp])
                        : "l"(ap[jp]), "l"(b2), "l"(MASK), "l"(w2));
                    // scalar e half: accE += sat(ea*eb) * asw
                    float e0, e1;
                    MULSAT(e0, eav[2 * jp],     ebv[i]);
                    MULSAT(e1, eav[2 * jp + 1], ebv[i]);
                    accE[i][2 * jp]     = fmaf(e0, asw, accE[i][2 * jp]);
                    accE[i][2 * jp + 1] = fmaf(e1, asw, accE[i][2 * jp + 1]);
                }
            }
        }
    }

    // epilogue: + P[j] + Q[i] + c0, hard_sigmoid
    const float c0 = g_c0;
    float4 Pv = *reinterpret_cast<const float4*>(&g_P[j0 + tx * 4]);
    #pragma unroll
    for (int i = 0; i < 4; i++) {
        int   irow = i0 + ty * 4 + i;
        float base = g_Q[irow] + c0 + 3.0f;
        float p0, p1, p2, p3;
        UNPACK2(p0, p1, accP[i][0]);
        UNPACK2(p2, p3, accP[i][1]);
        float4 o;
        o.x = fminf(fmaxf(p0 + accE[i][0] + Pv.x + base, 0.f), 6.f) * (1.f / 6.f);
        o.y = fminf(fmaxf(p1 + accE[i][1] + Pv.y + base, 0.f), 6.f) * (1.f / 6.f);
        o.z = fminf(fmaxf(p2 + accE[i][2] + Pv.z + base, 0.f), 6.f) * (1.f / 6.f);
        o.w = fminf(fmaxf(p3 + accE[i][3] + Pv.w + base, 0.f), 6.f) * (1.f / 6.f);
        *reinterpret_cast<float4*>(&out[irow * NN + j0 + tx * 4]) = o;
    }
}

// ---------------------------------------------------------------------------
extern "C" void kernel_launch(void* const* d_in, const int* in_sizes, int n_in,
                              void* d_out, int out_size) {
    const float* x     = (const float*)d_in[0];
    const float* W_enc = (const float*)d_in[1];
    const float* b_enc = (const float*)d_in[2];
    const float* W1    = (const float*)d_in[3];
    const float* b1    = (const float*)d_in[4];
    const float* W2    = (const float*)d_in[5];
    const float* b2    = (const float*)d_in[6];
    float* out = (float*)d_out;

    aux_kernel<<<NN / 4, 256>>>(x, W_enc, b_enc, W1, b1, W2, b2);

    dim3 grid(NN / 64, NN / 64);
    main_kernel<<<grid, 256>>>(out);
}